// round 1
// baseline (speedup 1.0000x reference)
#include <cuda_runtime.h>
#include <math.h>

#define NMAX 100000

// Scratch: per-node frame Q (3 columns as float4, validity in [0].w) and node feats.
__device__ float4 g_q[NMAX * 3];
__device__ float4 g_nf[NMAX];

struct F3 { float x, y, z; };
__device__ __forceinline__ F3 mk3(float a, float b, float c) { F3 r; r.x = a; r.y = b; r.z = c; return r; }
__device__ __forceinline__ F3 sub3(F3 a, F3 b) { return mk3(a.x - b.x, a.y - b.y, a.z - b.z); }
__device__ __forceinline__ float dot3(F3 a, F3 b) { return a.x * b.x + a.y * b.y + a.z * b.z; }
__device__ __forceinline__ F3 cross3(F3 a, F3 b) {
    return mk3(a.y * b.z - a.z * b.y, a.z * b.x - a.x * b.z, a.x * b.y - a.y * b.x);
}
// _normalize semantics of the reference: x / max(||x||, 1e-12)
__device__ __forceinline__ F3 nrm3(F3 a) {
    float n = sqrtf(dot3(a, a));
    float s = 1.0f / fmaxf(n, 1e-12f);
    return mk3(a.x * s, a.y * s, a.z * s);
}
__device__ __forceinline__ float signf_(float x) { return (float)((x > 0.0f) - (x < 0.0f)); }

// ---------------------------------------------------------------------------
// Kernel 1: per-node geometry -> node feats (4) + frame Q (3 cols) + valid
// ---------------------------------------------------------------------------
__global__ void k_node_geom(const float* __restrict__ X, const int* __restrict__ batch, int N)
{
    int i = blockIdx.x * blockDim.x + threadIdx.x;
    if (i >= N) return;

    auto ldx = [&](int j) -> F3 {
        j = j < 0 ? 0 : (j > N - 1 ? N - 1 : j);
        return mk3(X[3 * j], X[3 * j + 1], X[3 * j + 2]);
    };
    F3 xm1 = ldx(i - 1), x0 = ldx(i), xp1 = ldx(i + 1), xp2 = ldx(i + 2);

    // bnd[j] = (j>0) && batch[j]!=batch[j-1]; shiftl gives false OOB
    int bi   = (i > 0)     && (batch[i] != batch[i - 1]);
    int bip1 = (i + 1 < N) && (batch[i + 1] != batch[i]);
    int bip2 = (i + 2 < N) && (batch[i + 2] != batch[i + 1]);
    bool bad_a = bi || bip1 || (i == 0) || (i == N - 1);
    bool bad_d = bi || bip1 || bip2 || (i == 0) || (i >= N - 2);

    F3 Um = nrm3(sub3(x0,  xm1));   // U[i-1]
    F3 Uc = nrm3(sub3(xp1, x0));    // U[i]
    F3 Up = nrm3(sub3(xp2, xp1));   // U[i+1]

    // Dihedral at node i: c1 = n(cross(U[i-1],U[i])), c2 = n(cross(U[i],U[i+1]))
    F3 c1 = nrm3(cross3(Um, Uc));
    F3 c2 = nrm3(cross3(Uc, Up));
    float cosd = fminf(fmaxf(dot3(c1, c2), -1.0f + 1e-6f), 1.0f - 1e-6f);
    float sg = signf_(dot3(c2, Um));
    // sin(s*acos(x)) = s*sqrt(1-x^2); cos(s*acos(x)) = x for s=+-1, = 1 for s=0
    float sdih = sg * sqrtf(fmaxf(1.0f - cosd * cosd, 0.0f));
    float cdih = (sg == 0.0f) ? 1.0f : cosd;

    // Angle at node i: d0 = n(X[i-1]-X[i]), d1 = n(X[i+1]-X[i])
    F3 d0 = nrm3(sub3(xm1, x0));
    F3 d1 = nrm3(sub3(xp1, x0));
    float cosa = dot3(d0, d1);
    float sina = sqrtf(1.0f - cosa * cosa + 1e-6f);

    float4 nf;
    nf.x = bad_d ? 0.0f : sdih;
    nf.y = bad_d ? 0.0f : cdih;
    nf.z = bad_a ? 0.0f : sina;
    nf.w = bad_a ? 0.0f : cosa;
    g_nf[i] = nf;

    // Local frame Q: columns bvec, nvec, cross(bvec,nvec); zeroed when bad_a
    F3 bv = nrm3(sub3(Um, Uc));
    F3 nv = nrm3(cross3(Um, Uc));
    F3 cv = cross3(bv, nv);
    float m = bad_a ? 0.0f : 1.0f;
    g_q[i * 3 + 0] = make_float4(bv.x * m, bv.y * m, bv.z * m, m);
    g_q[i * 3 + 1] = make_float4(nv.x * m, nv.y * m, nv.z * m, 0.0f);
    g_q[i * 3 + 2] = make_float4(cv.x * m, cv.y * m, cv.z * m, 0.0f);
}

// ---------------------------------------------------------------------------
// Warp LayerNorm helper: lane owns 4 contiguous columns (4*lane .. 4*lane+3)
// ---------------------------------------------------------------------------
__device__ __forceinline__ void ln_store(float4 a, float4 gg, float4 bt, float* __restrict__ dst)
{
    float s1 = a.x + a.y + a.z + a.w;
    float s2 = a.x * a.x + a.y * a.y + a.z * a.z + a.w * a.w;
#pragma unroll
    for (int o = 16; o > 0; o >>= 1) {
        s1 += __shfl_xor_sync(0xffffffffu, s1, o);
        s2 += __shfl_xor_sync(0xffffffffu, s2, o);
    }
    float mean = s1 * (1.0f / 128.0f);
    float var  = fmaxf(s2 * (1.0f / 128.0f) - mean * mean, 0.0f);
    float inv  = rsqrtf(var + 1e-5f);
    float4 o4;
    o4.x = (a.x - mean) * inv * gg.x + bt.x;
    o4.y = (a.y - mean) * inv * gg.y + bt.y;
    o4.z = (a.z - mean) * inv * gg.z + bt.z;
    o4.w = (a.w - mean) * inv * gg.w + bt.w;
    *reinterpret_cast<float4*>(dst) = o4;
}

// ---------------------------------------------------------------------------
// Kernel 2: h_V = LN(feat(4) @ W_node + b) * g + beta, 1 warp per node
// ---------------------------------------------------------------------------
__global__ void k_node_out(const float* __restrict__ Wn, const float* __restrict__ bn,
                           const float* __restrict__ gn, const float* __restrict__ bet,
                           float* __restrict__ hV, int N)
{
    int gw   = (blockIdx.x * blockDim.x + threadIdx.x) >> 5;
    int lane = threadIdx.x & 31;
    if (gw >= N) return;
    int c = 4 * lane;
    float4 w0 = *reinterpret_cast<const float4*>(Wn + 0 * 128 + c);
    float4 w1 = *reinterpret_cast<const float4*>(Wn + 1 * 128 + c);
    float4 w2 = *reinterpret_cast<const float4*>(Wn + 2 * 128 + c);
    float4 w3 = *reinterpret_cast<const float4*>(Wn + 3 * 128 + c);
    float4 bb = *reinterpret_cast<const float4*>(bn + c);
    float4 gg = *reinterpret_cast<const float4*>(gn + c);
    float4 bt = *reinterpret_cast<const float4*>(bet + c);

    float4 f = g_nf[gw];
    float4 a;
    a.x = bb.x + f.x * w0.x + f.y * w1.x + f.z * w2.x + f.w * w3.x;
    a.y = bb.y + f.x * w0.y + f.y * w1.y + f.z * w2.y + f.w * w3.y;
    a.z = bb.z + f.x * w0.z + f.y * w1.z + f.z * w2.z + f.w * w3.z;
    a.w = bb.w + f.x * w0.w + f.y * w1.w + f.z * w2.w + f.w * w3.w;
    ln_store(a, gg, bt, hV + (size_t)gw * 128 + c);
}

// ---------------------------------------------------------------------------
// Kernel 3: edges. 1 warp per edge (grid-stride), W_edge register-resident.
// Feature vector (23) distributed one-per-lane, broadcast via shfl.
// ---------------------------------------------------------------------------
__global__ void __launch_bounds__(128)
k_edge(const float* __restrict__ X, const int* __restrict__ ei, int E,
       const float* __restrict__ We, const float* __restrict__ be,
       const float* __restrict__ ge, const float* __restrict__ bet,
       float* __restrict__ hE)
{
    int lane = threadIdx.x & 31;
    int gw   = (blockIdx.x * blockDim.x + threadIdx.x) >> 5;
    int nw   = (gridDim.x * blockDim.x) >> 5;
    int c = 4 * lane;

    float4 w[23];
#pragma unroll
    for (int k = 0; k < 23; k++) w[k] = *reinterpret_cast<const float4*>(We + k * 128 + c);
    float4 bb = *reinterpret_cast<const float4*>(be + c);
    float4 gg = *reinterpret_cast<const float4*>(ge + c);
    float4 bt = *reinterpret_cast<const float4*>(bet + c);

    for (int e = gw; e < E; e += nw) {
        int s = __ldg(ei + e);
        int t = __ldg(ei + E + e);

        float4 tb = g_q[t * 3 + 0], tn = g_q[t * 3 + 1], tc = g_q[t * 3 + 2];
        float4 sb = g_q[s * 3 + 0], sn = g_q[s * 3 + 1], sc = g_q[s * 3 + 2];

        float dvx = __ldg(X + 3 * s)     - __ldg(X + 3 * t);
        float dvy = __ldg(X + 3 * s + 1) - __ldg(X + 3 * t + 1);
        float dvz = __ldg(X + 3 * s + 2) - __ldg(X + 3 * t + 2);
        float d2   = dvx * dvx + dvy * dvy + dvz * dvz;
        float dist = sqrtf(d2 + 1e-6f);
        float rinv = 1.0f / fmaxf(sqrtf(d2), 1e-12f);
        float dhx = dvx * rinv, dhy = dvy * rinv, dhz = dvz * rinv;

        // R = Q_tgt^T * Q_src ; rows of Q^T are stored columns
        float Rxx = tb.x * sb.x + tb.y * sb.y + tb.z * sb.z;
        float Rxy = tb.x * sn.x + tb.y * sn.y + tb.z * sn.z;
        float Rxz = tb.x * sc.x + tb.y * sc.y + tb.z * sc.z;
        float Ryx = tn.x * sb.x + tn.y * sb.y + tn.z * sb.z;
        float Ryy = tn.x * sn.x + tn.y * sn.y + tn.z * sn.z;
        float Ryz = tn.x * sc.x + tn.y * sc.y + tn.z * sc.z;
        float Rzx = tc.x * sb.x + tc.y * sb.y + tc.z * sb.z;
        float Rzy = tc.x * sn.x + tc.y * sn.y + tc.z * sn.z;
        float Rzz = tc.x * sc.x + tc.y * sc.y + tc.z * sc.z;

        // Quaternion of R (reference _quaternions)
        float m0 = 0.5f * sqrtf(fabsf(1.0f + Rxx - Ryy - Rzz));
        float m1 = 0.5f * sqrtf(fabsf(1.0f - Rxx + Ryy - Rzz));
        float m2 = 0.5f * sqrtf(fabsf(1.0f - Rxx - Ryy + Rzz));
        float q0 = signf_(Rzy - Ryz) * m0;
        float q1 = signf_(Rxz - Rzx) * m1;
        float q2 = signf_(Ryx - Rxy) * m2;
        float qw = 0.5f * sqrtf(fmaxf(1.0f + Rxx + Ryy + Rzz, 0.0f));
        float qn = sqrtf(q0 * q0 + q1 * q1 + q2 * q2 + qw * qw);
        float vm = (tb.w * sb.w) / fmaxf(qn, 1e-12f);  // validity * 1/norm
        q0 *= vm; q1 *= vm; q2 *= vm; qw *= vm;

        // direct = Q_tgt^T * dhat (Q zeroed when invalid -> mask is automatic)
        float di0 = tb.x * dhx + tb.y * dhy + tb.z * dhz;
        float di1 = tn.x * dhx + tn.y * dhy + tn.z * dhz;
        float di2 = tc.x * dhx + tc.y * dhy + tc.z * dhz;

        // Feature k lives on lane k: [q0,q1,q2,qw, rbf0..15, di0,di1,di2]
        float myfeat;
        if (lane < 4) {
            myfeat = lane == 0 ? q0 : lane == 1 ? q1 : lane == 2 ? q2 : qw;
        } else if (lane < 20) {
            float mu = (float)(lane - 4) * (20.0f / 15.0f);
            float tt = (dist - mu) * 0.8f;
            myfeat = __expf(-tt * tt);
        } else {
            myfeat = lane == 20 ? di0 : lane == 21 ? di1 : lane == 22 ? di2 : 0.0f;
        }

        float4 a = bb;
#pragma unroll
        for (int k = 0; k < 23; k++) {
            float fk = __shfl_sync(0xffffffffu, myfeat, k);
            a.x = fmaf(fk, w[k].x, a.x);
            a.y = fmaf(fk, w[k].y, a.y);
            a.z = fmaf(fk, w[k].z, a.z);
            a.w = fmaf(fk, w[k].w, a.w);
        }
        ln_store(a, gg, bt, hE + (size_t)e * 128 + c);
    }
}

// ---------------------------------------------------------------------------
extern "C" void kernel_launch(void* const* d_in, const int* in_sizes, int n_in,
                              void* d_out, int out_size)
{
    const float* X    = (const float*)d_in[0];
    const int*   bat  = (const int*)d_in[1];
    const int*   ei   = (const int*)d_in[2];
    const float* Wn   = (const float*)d_in[3];
    const float* bn   = (const float*)d_in[4];
    const float* gn   = (const float*)d_in[5];
    const float* btn  = (const float*)d_in[6];
    const float* We   = (const float*)d_in[7];
    const float* be   = (const float*)d_in[8];
    const float* ge   = (const float*)d_in[9];
    const float* bte  = (const float*)d_in[10];

    int N = in_sizes[0] / 3;
    int E = in_sizes[2] / 2;

    float* hV = (float*)d_out;
    float* hE = hV + (size_t)N * 128;

    k_node_geom<<<(N + 255) / 256, 256>>>(X, bat, N);
    k_node_out<<<(N * 32 + 255) / 256, 256>>>(Wn, bn, gn, btn, hV, N);
    k_edge<<<1480, 128>>>(X, ei, E, We, be, ge, bte, hE);
}

// round 2
// speedup vs baseline: 12.4446x; 12.4446x over previous
#include <cuda_runtime.h>
#include <math.h>

#define NMAX 100000
#define EMAX 1000000

// Scratch (module-static, no runtime allocation):
__device__ float4 g_q[NMAX * 3];       // per-node frame (3 cols), valid flag in [0].w
__device__ float4 g_nf[NMAX];          // per-node 4 features
__device__ float4 g_feat[EMAX * 6];    // per-edge 24 floats (23 feats + pad)

struct F3 { float x, y, z; };
__device__ __forceinline__ F3 mk3(float a, float b, float c) { F3 r; r.x = a; r.y = b; r.z = c; return r; }
__device__ __forceinline__ F3 sub3(F3 a, F3 b) { return mk3(a.x - b.x, a.y - b.y, a.z - b.z); }
__device__ __forceinline__ float dot3(F3 a, F3 b) { return a.x * b.x + a.y * b.y + a.z * b.z; }
__device__ __forceinline__ F3 cross3(F3 a, F3 b) {
    return mk3(a.y * b.z - a.z * b.y, a.z * b.x - a.x * b.z, a.x * b.y - a.y * b.x);
}
__device__ __forceinline__ F3 nrm3(F3 a) {
    float n = sqrtf(dot3(a, a));
    float s = 1.0f / fmaxf(n, 1e-12f);
    return mk3(a.x * s, a.y * s, a.z * s);
}
__device__ __forceinline__ float signf_(float x) { return (float)((x > 0.0f) - (x < 0.0f)); }

// packed f32x2 helpers
__device__ __forceinline__ unsigned long long dup2(float f) {
    unsigned long long p;
    unsigned u = __float_as_uint(f);
    asm("mov.b64 %0, {%1, %1};" : "=l"(p) : "r"(u));
    return p;
}
__device__ __forceinline__ unsigned long long pack2(float a, float b) {
    unsigned long long p;
    unsigned ua = __float_as_uint(a), ub = __float_as_uint(b);
    asm("mov.b64 %0, {%1, %2};" : "=l"(p) : "r"(ua), "r"(ub));
    return p;
}
__device__ __forceinline__ void unpack2(unsigned long long p, float& a, float& b) {
    unsigned ua, ub;
    asm("mov.b64 {%0, %1}, %2;" : "=r"(ua), "=r"(ub) : "l"(p));
    a = __uint_as_float(ua); b = __uint_as_float(ub);
}
__device__ __forceinline__ void ffma2(unsigned long long& d, unsigned long long a, unsigned long long b) {
    asm("fma.rn.f32x2 %0, %1, %2, %0;" : "+l"(d) : "l"(a), "l"(b));
}

// ---------------------------------------------------------------------------
// Kernel 1: per-node geometry -> node feats (4) + frame Q (3 cols) + valid
// ---------------------------------------------------------------------------
__global__ void k_node_geom(const float* __restrict__ X, const int* __restrict__ batch, int N)
{
    int i = blockIdx.x * blockDim.x + threadIdx.x;
    if (i >= N) return;

    auto ldx = [&](int j) -> F3 {
        j = j < 0 ? 0 : (j > N - 1 ? N - 1 : j);
        return mk3(X[3 * j], X[3 * j + 1], X[3 * j + 2]);
    };
    F3 xm1 = ldx(i - 1), x0 = ldx(i), xp1 = ldx(i + 1), xp2 = ldx(i + 2);

    int bi   = (i > 0)     && (batch[i] != batch[i - 1]);
    int bip1 = (i + 1 < N) && (batch[i + 1] != batch[i]);
    int bip2 = (i + 2 < N) && (batch[i + 2] != batch[i + 1]);
    bool bad_a = bi || bip1 || (i == 0) || (i == N - 1);
    bool bad_d = bi || bip1 || bip2 || (i == 0) || (i >= N - 2);

    F3 Um = nrm3(sub3(x0,  xm1));
    F3 Uc = nrm3(sub3(xp1, x0));
    F3 Up = nrm3(sub3(xp2, xp1));

    F3 c1 = nrm3(cross3(Um, Uc));
    F3 c2 = nrm3(cross3(Uc, Up));
    float cosd = fminf(fmaxf(dot3(c1, c2), -1.0f + 1e-6f), 1.0f - 1e-6f);
    float sg = signf_(dot3(c2, Um));
    float sdih = sg * sqrtf(fmaxf(1.0f - cosd * cosd, 0.0f));
    float cdih = (sg == 0.0f) ? 1.0f : cosd;

    F3 d0 = nrm3(sub3(xm1, x0));
    F3 d1 = nrm3(sub3(xp1, x0));
    float cosa = dot3(d0, d1);
    float sina = sqrtf(1.0f - cosa * cosa + 1e-6f);

    float4 nf;
    nf.x = bad_d ? 0.0f : sdih;
    nf.y = bad_d ? 0.0f : cdih;
    nf.z = bad_a ? 0.0f : sina;
    nf.w = bad_a ? 0.0f : cosa;
    g_nf[i] = nf;

    F3 bv = nrm3(sub3(Um, Uc));
    F3 nv = nrm3(cross3(Um, Uc));
    F3 cv = cross3(bv, nv);
    float m = bad_a ? 0.0f : 1.0f;
    g_q[i * 3 + 0] = make_float4(bv.x * m, bv.y * m, bv.z * m, m);
    g_q[i * 3 + 1] = make_float4(nv.x * m, nv.y * m, nv.z * m, 0.0f);
    g_q[i * 3 + 2] = make_float4(cv.x * m, cv.y * m, cv.z * m, 0.0f);
}

// ---------------------------------------------------------------------------
// Warp LayerNorm helper: lane owns 4 contiguous columns
// ---------------------------------------------------------------------------
__device__ __forceinline__ void ln_store(float4 a, float4 gg, float4 bt, float* __restrict__ dst)
{
    float s1 = a.x + a.y + a.z + a.w;
    float s2 = a.x * a.x + a.y * a.y + a.z * a.z + a.w * a.w;
#pragma unroll
    for (int o = 16; o > 0; o >>= 1) {
        s1 += __shfl_xor_sync(0xffffffffu, s1, o);
        s2 += __shfl_xor_sync(0xffffffffu, s2, o);
    }
    float mean = s1 * (1.0f / 128.0f);
    float var  = fmaxf(s2 * (1.0f / 128.0f) - mean * mean, 0.0f);
    float inv  = rsqrtf(var + 1e-5f);
    float4 o4;
    o4.x = (a.x - mean) * inv * gg.x + bt.x;
    o4.y = (a.y - mean) * inv * gg.y + bt.y;
    o4.z = (a.z - mean) * inv * gg.z + bt.z;
    o4.w = (a.w - mean) * inv * gg.w + bt.w;
    *reinterpret_cast<float4*>(dst) = o4;
}

// ---------------------------------------------------------------------------
// Kernel 2: h_V = LN(feat(4) @ W_node + b) * g + beta, 1 warp per node
// ---------------------------------------------------------------------------
__global__ void k_node_out(const float* __restrict__ Wn, const float* __restrict__ bn,
                           const float* __restrict__ gn, const float* __restrict__ bet,
                           float* __restrict__ hV, int N)
{
    int gw   = (blockIdx.x * blockDim.x + threadIdx.x) >> 5;
    int lane = threadIdx.x & 31;
    if (gw >= N) return;
    int c = 4 * lane;
    float4 w0 = *reinterpret_cast<const float4*>(Wn + 0 * 128 + c);
    float4 w1 = *reinterpret_cast<const float4*>(Wn + 1 * 128 + c);
    float4 w2 = *reinterpret_cast<const float4*>(Wn + 2 * 128 + c);
    float4 w3 = *reinterpret_cast<const float4*>(Wn + 3 * 128 + c);
    float4 bb = *reinterpret_cast<const float4*>(bn + c);
    float4 gg = *reinterpret_cast<const float4*>(gn + c);
    float4 bt = *reinterpret_cast<const float4*>(bet + c);

    float4 f = g_nf[gw];
    float4 a;
    a.x = bb.x + f.x * w0.x + f.y * w1.x + f.z * w2.x + f.w * w3.x;
    a.y = bb.y + f.x * w0.y + f.y * w1.y + f.z * w2.y + f.w * w3.y;
    a.z = bb.z + f.x * w0.z + f.y * w1.z + f.z * w2.z + f.w * w3.z;
    a.w = bb.w + f.x * w0.w + f.y * w1.w + f.z * w2.w + f.w * w3.w;
    ln_store(a, gg, bt, hV + (size_t)gw * 128 + c);
}

// ---------------------------------------------------------------------------
// Kernel 3a: per-edge features, ONE THREAD PER EDGE -> g_feat[e][24]
// ---------------------------------------------------------------------------
__global__ void __launch_bounds__(256)
k_edge_feat(const float* __restrict__ X, const int* __restrict__ ei, int E)
{
    int e = blockIdx.x * blockDim.x + threadIdx.x;
    if (e >= E) return;
    int s = __ldg(ei + e);
    int t = __ldg(ei + E + e);

    float4 tb = g_q[t * 3 + 0], tn = g_q[t * 3 + 1], tc = g_q[t * 3 + 2];
    float4 sb = g_q[s * 3 + 0], sn = g_q[s * 3 + 1], sc = g_q[s * 3 + 2];

    float dvx = __ldg(X + 3 * s)     - __ldg(X + 3 * t);
    float dvy = __ldg(X + 3 * s + 1) - __ldg(X + 3 * t + 1);
    float dvz = __ldg(X + 3 * s + 2) - __ldg(X + 3 * t + 2);
    float d2   = dvx * dvx + dvy * dvy + dvz * dvz;
    float dist = sqrtf(d2 + 1e-6f);
    float rinv = 1.0f / fmaxf(sqrtf(d2), 1e-12f);
    float dhx = dvx * rinv, dhy = dvy * rinv, dhz = dvz * rinv;

    // R = Q_tgt^T * Q_src
    float Rxx = tb.x * sb.x + tb.y * sb.y + tb.z * sb.z;
    float Rxy = tb.x * sn.x + tb.y * sn.y + tb.z * sn.z;
    float Rxz = tb.x * sc.x + tb.y * sc.y + tb.z * sc.z;
    float Ryx = tn.x * sb.x + tn.y * sb.y + tn.z * sb.z;
    float Ryy = tn.x * sn.x + tn.y * sn.y + tn.z * sn.z;
    float Ryz = tn.x * sc.x + tn.y * sc.y + tn.z * sc.z;
    float Rzx = tc.x * sb.x + tc.y * sb.y + tc.z * sb.z;
    float Rzy = tc.x * sn.x + tc.y * sn.y + tc.z * sn.z;
    float Rzz = tc.x * sc.x + tc.y * sc.y + tc.z * sc.z;

    float m0 = 0.5f * sqrtf(fabsf(1.0f + Rxx - Ryy - Rzz));
    float m1 = 0.5f * sqrtf(fabsf(1.0f - Rxx + Ryy - Rzz));
    float m2 = 0.5f * sqrtf(fabsf(1.0f - Rxx - Ryy + Rzz));
    float q0 = signf_(Rzy - Ryz) * m0;
    float q1 = signf_(Rxz - Rzx) * m1;
    float q2 = signf_(Ryx - Rxy) * m2;
    float qw = 0.5f * sqrtf(fmaxf(1.0f + Rxx + Ryy + Rzz, 0.0f));
    float qn = sqrtf(q0 * q0 + q1 * q1 + q2 * q2 + qw * qw);
    float vm = (tb.w * sb.w) / fmaxf(qn, 1e-12f);

    float di0 = tb.x * dhx + tb.y * dhy + tb.z * dhz;
    float di1 = tn.x * dhx + tn.y * dhy + tn.z * dhz;
    float di2 = tc.x * dhx + tc.y * dhy + tc.z * dhz;

    float rbf[16];
#pragma unroll
    for (int k = 0; k < 16; k++) {
        float mu = (float)k * (20.0f / 15.0f);
        float tt = (dist - mu) * 0.8f;
        rbf[k] = __expf(-tt * tt);
    }

    float4* fo = g_feat + (size_t)e * 6;
    fo[0] = make_float4(q0 * vm, q1 * vm, q2 * vm, qw * vm);
    fo[1] = make_float4(rbf[0],  rbf[1],  rbf[2],  rbf[3]);
    fo[2] = make_float4(rbf[4],  rbf[5],  rbf[6],  rbf[7]);
    fo[3] = make_float4(rbf[8],  rbf[9],  rbf[10], rbf[11]);
    fo[4] = make_float4(rbf[12], rbf[13], rbf[14], rbf[15]);
    fo[5] = make_float4(di0, di1, di2, 0.0f);
}

// ---------------------------------------------------------------------------
// Kernel 3b: h_E = LN(feat(23) @ W_edge + b) * g + beta
// warp handles 4 edges per iteration; W in shared memory; packed f32x2 FMA
// ---------------------------------------------------------------------------
__global__ void __launch_bounds__(256)
k_edge_gemm(const float* __restrict__ We, const float* __restrict__ be,
            const float* __restrict__ ge, const float* __restrict__ bet,
            float* __restrict__ hE, int E)
{
    __shared__ float4 sW[23 * 32];
    int tid = threadIdx.x;
    // We is row-major [23][128]; float4 index k*32+lane matches linear order
    for (int i = tid; i < 23 * 32; i += 256)
        sW[i] = reinterpret_cast<const float4*>(We)[i];
    __syncthreads();

    int lane = tid & 31;
    int gw   = (blockIdx.x * blockDim.x + tid) >> 5;
    int nw   = (gridDim.x * blockDim.x) >> 5;
    int c = 4 * lane;
    float4 bb = *reinterpret_cast<const float4*>(be + c);
    float4 gg = *reinterpret_cast<const float4*>(ge + c);
    float4 bt = *reinterpret_cast<const float4*>(bet + c);
    unsigned long long bias0 = pack2(bb.x, bb.y);
    unsigned long long bias1 = pack2(bb.z, bb.w);

    const float* featf = reinterpret_cast<const float*>(g_feat);

    for (int base = gw * 4; base < E; base += nw * 4) {
        float f[4];
#pragma unroll
        for (int j = 0; j < 4; j++) {
            int e = base + j;
            f[j] = (lane < 24 && e < E) ? featf[(size_t)e * 24 + lane] : 0.0f;
        }

        unsigned long long acc[4][2];
#pragma unroll
        for (int j = 0; j < 4; j++) { acc[j][0] = bias0; acc[j][1] = bias1; }

#pragma unroll
        for (int k = 0; k < 23; k++) {
            ulonglong2 w2 = *reinterpret_cast<const ulonglong2*>(&sW[k * 32 + lane]);
#pragma unroll
            for (int j = 0; j < 4; j++) {
                unsigned long long fp = dup2(__shfl_sync(0xffffffffu, f[j], k));
                ffma2(acc[j][0], w2.x, fp);
                ffma2(acc[j][1], w2.y, fp);
            }
        }

#pragma unroll
        for (int j = 0; j < 4; j++) {
            int e = base + j;
            float4 a;
            unpack2(acc[j][0], a.x, a.y);
            unpack2(acc[j][1], a.z, a.w);
            if (e < E)
                ln_store(a, gg, bt, hE + (size_t)e * 128 + c);
        }
    }
}

// ---------------------------------------------------------------------------
extern "C" void kernel_launch(void* const* d_in, const int* in_sizes, int n_in,
                              void* d_out, int out_size)
{
    const float* X    = (const float*)d_in[0];
    const int*   bat  = (const int*)d_in[1];
    const int*   ei   = (const int*)d_in[2];
    const float* Wn   = (const float*)d_in[3];
    const float* bn   = (const float*)d_in[4];
    const float* gn   = (const float*)d_in[5];
    const float* btn  = (const float*)d_in[6];
    const float* We   = (const float*)d_in[7];
    const float* be   = (const float*)d_in[8];
    const float* ge   = (const float*)d_in[9];
    const float* bte  = (const float*)d_in[10];

    int N = in_sizes[0] / 3;
    int E = in_sizes[2] / 2;

    float* hV = (float*)d_out;
    float* hE = hV + (size_t)N * 128;

    k_node_geom<<<(N + 255) / 256, 256>>>(X, bat, N);
    k_node_out<<<(N * 32 + 255) / 256, 256>>>(Wn, bn, gn, btn, hV, N);
    k_edge_feat<<<(E + 255) / 256, 256>>>(X, ei, E);
    k_edge_gemm<<<1184, 256>>>(We, be, ge, bte, hE, E);
}